// round 3
// baseline (speedup 1.0000x reference)
#include <cuda_runtime.h>
#include <math.h>

#define S_LEN 2048
#define D_DIM 4096
#define NH    32
#define HD    128

// Scratch (allocation-free rule: __device__ globals, referenced directly
// from device code — no host-side symbol lookup needed)
__device__ float g_q[S_LEN * D_DIM];
__device__ float g_k[S_LEN * D_DIM];
__device__ float g_v[S_LEN * D_DIM];
__device__ float g_att[S_LEN * D_DIM];

// ---------------------------------------------------------------------------
// SGEMM NT:  C[M,N] = A[M,K] * B[N,K]^T   (both row-major, K contiguous)
// Tiles: BM=BN=128, BK=16, 256 threads, 8x8 microtile per thread.
// A and C are selected from the __device__ scratch arrays (or harness
// pointers) via small enums so no host symbol lookup is required.
// ---------------------------------------------------------------------------
#define BM 128
#define BN 128
#define BK 16

__device__ __forceinline__
void sgemm_nt_body(const float* __restrict__ A, const float* __restrict__ B,
                   float* __restrict__ C, int K, int N)
{
    __shared__ float As[BK][BM];
    __shared__ float Bs[BK][BN];

    const int tid = threadIdx.x;
    const int tx  = tid & 15;       // 0..15  -> n microtile
    const int ty  = tid >> 4;       // 0..15  -> m microtile
    const int mBase = blockIdx.y * BM;
    const int nBase = blockIdx.x * BN;

    const int r0 = tid >> 2;        // 0..63 loader row
    const int v  = tid & 3;         // 0..3  loader float4 slot

    const float* pA0 = A + (size_t)(mBase + r0)      * K + v * 4;
    const float* pA1 = A + (size_t)(mBase + r0 + 64) * K + v * 4;
    const float* pB0 = B + (size_t)(nBase + r0)      * K + v * 4;
    const float* pB1 = B + (size_t)(nBase + r0 + 64) * K + v * 4;

    float acc[8][8];
#pragma unroll
    for (int i = 0; i < 8; i++)
#pragma unroll
        for (int j = 0; j < 8; j++) acc[i][j] = 0.f;

    for (int k0 = 0; k0 < K; k0 += BK) {
        float4 a0 = *(const float4*)(pA0 + k0);
        float4 a1 = *(const float4*)(pA1 + k0);
        float4 b0 = *(const float4*)(pB0 + k0);
        float4 b1 = *(const float4*)(pB1 + k0);

        __syncthreads();   // prior compute done reading smem

        As[v*4+0][r0]    = a0.x; As[v*4+1][r0]    = a0.y;
        As[v*4+2][r0]    = a0.z; As[v*4+3][r0]    = a0.w;
        As[v*4+0][r0+64] = a1.x; As[v*4+1][r0+64] = a1.y;
        As[v*4+2][r0+64] = a1.z; As[v*4+3][r0+64] = a1.w;

        Bs[v*4+0][r0]    = b0.x; Bs[v*4+1][r0]    = b0.y;
        Bs[v*4+2][r0]    = b0.z; Bs[v*4+3][r0]    = b0.w;
        Bs[v*4+0][r0+64] = b1.x; Bs[v*4+1][r0+64] = b1.y;
        Bs[v*4+2][r0+64] = b1.z; Bs[v*4+3][r0+64] = b1.w;

        __syncthreads();

#pragma unroll
        for (int k = 0; k < BK; k++) {
            float a[8], b[8];
            *(float4*)(a)     = *(const float4*)(&As[k][ty*8]);
            *(float4*)(a + 4) = *(const float4*)(&As[k][ty*8 + 4]);
            *(float4*)(b)     = *(const float4*)(&Bs[k][tx*8]);
            *(float4*)(b + 4) = *(const float4*)(&Bs[k][tx*8 + 4]);
#pragma unroll
            for (int i = 0; i < 8; i++)
#pragma unroll
                for (int j = 0; j < 8; j++)
                    acc[i][j] += a[i] * b[j];
        }
    }

#pragma unroll
    for (int i = 0; i < 8; i++) {
        float4* cp = (float4*)(C + (size_t)(mBase + ty*8 + i) * N + nBase + tx*8);
        cp[0] = make_float4(acc[i][0], acc[i][1], acc[i][2], acc[i][3]);
        cp[1] = make_float4(acc[i][4], acc[i][5], acc[i][6], acc[i][7]);
    }
}

// QKV projections: one kernel, 3 GEMMs selected by blockIdx.z.
__global__ __launch_bounds__(256, 2)
void qkv_gemm_kernel(const float* __restrict__ x,
                     const float* __restrict__ wq,
                     const float* __restrict__ wk,
                     const float* __restrict__ wv)
{
    const float* B;
    float* C;
    if (blockIdx.z == 0)      { B = wq; C = g_q; }
    else if (blockIdx.z == 1) { B = wk; C = g_k; }
    else                      { B = wv; C = g_v; }
    sgemm_nt_body(x, B, C, D_DIM, D_DIM);
}

// Output projection: A = g_att (device global), C = harness d_out.
__global__ __launch_bounds__(256, 2)
void out_gemm_kernel(const float* __restrict__ wo, float* __restrict__ out)
{
    sgemm_nt_body(g_att, wo, out, D_DIM, D_DIM);
}

// ---------------------------------------------------------------------------
// RoPE (interleaved pairs), applied in-place to g_q and g_k.
// ---------------------------------------------------------------------------
__global__ void rope_kernel(const float* __restrict__ fcos,
                            const float* __restrict__ fsin)
{
    int idx = blockIdx.x * blockDim.x + threadIdx.x;
    if (idx >= S_LEN * NH * (HD / 2)) return;
    int s = idx >> 11;           // / (NH * 64)
    int r = idx & 2047;
    int h = r >> 6;
    int i = r & 63;

    float c  = fcos[s * 64 + i];
    float sn = fsin[s * 64 + i];
    size_t base = (size_t)s * D_DIM + h * HD + 2 * i;

    float qr = g_q[base], qi = g_q[base + 1];
    g_q[base]     = qr * c - qi * sn;
    g_q[base + 1] = qr * sn + qi * c;

    float kr = g_k[base], ki = g_k[base + 1];
    g_k[base]     = kr * c - ki * sn;
    g_k[base + 1] = kr * sn + ki * c;
}

// ---------------------------------------------------------------------------
// Flash attention (causal), fp32. One CTA = (64-row Q tile) x (one head).
// 256 threads as 16x16; thread computes S rows ty*4+{0..3}, cols j*16+tx.
// Online softmax; O accum 4 rows x 8 cols per thread.
// smem: Qt[128][64] Kt[128][64] V[64][132] Pt[64][65]  = 113.25 KB dynamic
// ---------------------------------------------------------------------------
#define FA_SMEM_FLOATS (128*64 + 128*64 + 64*132 + 64*65)
#define FA_SMEM_BYTES  (FA_SMEM_FLOATS * 4)

__global__ __launch_bounds__(256, 1)
void flash_kernel()
{
    extern __shared__ float sm[];
    float* sQt = sm;                      // [128][64]  (d-major)
    float* sKt = sQt + 128 * 64;          // [128][64]
    float* sV  = sKt + 128 * 64;          // [64][132]  (row-major, padded)
    float* sPt = sV  + 64 * 132;          // [64][65]   (c-major, padded)

    const int h   = blockIdx.y;
    const int qt  = blockIdx.x;
    const int q0  = qt * 64;
    const int tid = threadIdx.x;
    const int tx  = tid & 15;
    const int ty  = tid >> 4;
    const float scale = 0.08838834764831845f;   // 1/sqrt(128)

    // Load Q tile transposed into sQt[d][m]
    {
        int m  = tid >> 2;
        int vb = tid & 3;
        const float* qp = g_q + (size_t)(q0 + m) * D_DIM + h * HD;
#pragma unroll
        for (int vv = vb; vv < 32; vv += 4) {
            float4 t = *(const float4*)(qp + vv * 4);
            int d = vv * 4;
            sQt[(d+0)*64 + m] = t.x; sQt[(d+1)*64 + m] = t.y;
            sQt[(d+2)*64 + m] = t.z; sQt[(d+3)*64 + m] = t.w;
        }
    }

    float acc[4][8];
#pragma unroll
    for (int i = 0; i < 4; i++)
#pragma unroll
        for (int j = 0; j < 8; j++) acc[i][j] = 0.f;

    float rmax[4] = {-INFINITY, -INFINITY, -INFINITY, -INFINITY};
    float rsum[4] = {0.f, 0.f, 0.f, 0.f};

    for (int jt = 0; jt <= qt; jt++) {
        const int k0 = jt * 64;

        __syncthreads();   // previous P.V reads done before overwrite

        // Load K tile (transposed) and V tile
        {
            int m  = tid >> 2;
            int vb = tid & 3;
            const float* kp = g_k + (size_t)(k0 + m) * D_DIM + h * HD;
            const float* vp = g_v + (size_t)(k0 + m) * D_DIM + h * HD;
#pragma unroll
            for (int vv = vb; vv < 32; vv += 4) {
                float4 t = *(const float4*)(kp + vv * 4);
                int d = vv * 4;
                sKt[(d+0)*64 + m] = t.x; sKt[(d+1)*64 + m] = t.y;
                sKt[(d+2)*64 + m] = t.z; sKt[(d+3)*64 + m] = t.w;
                *(float4*)(sV + m * 132 + vv * 4) = *(const float4*)(vp + vv * 4);
            }
        }
        __syncthreads();

        // S = Q K^T for this tile
        float s[4][4];
#pragma unroll
        for (int i = 0; i < 4; i++)
#pragma unroll
            for (int j = 0; j < 4; j++) s[i][j] = 0.f;

#pragma unroll 8
        for (int d = 0; d < 128; d++) {
            float qa[4], kb[4];
#pragma unroll
            for (int i = 0; i < 4; i++) qa[i] = sQt[d*64 + ty*4 + i];
#pragma unroll
            for (int j = 0; j < 4; j++) kb[j] = sKt[d*64 + j*16 + tx];
#pragma unroll
            for (int i = 0; i < 4; i++)
#pragma unroll
                for (int j = 0; j < 4; j++)
                    s[i][j] += qa[i] * kb[j];
        }

        // scale + causal mask (only diagonal tile is partial)
        if (jt == qt) {
#pragma unroll
            for (int i = 0; i < 4; i++)
#pragma unroll
                for (int j = 0; j < 4; j++) {
                    int col = j * 16 + tx;
                    int row = ty * 4 + i;
                    s[i][j] = (col > row) ? -1.0e9f : s[i][j] * scale;
                }
        } else {
#pragma unroll
            for (int i = 0; i < 4; i++)
#pragma unroll
                for (int j = 0; j < 4; j++) s[i][j] *= scale;
        }

        // row max across 16 lanes
        float tm[4];
#pragma unroll
        for (int i = 0; i < 4; i++) {
            tm[i] = fmaxf(fmaxf(s[i][0], s[i][1]), fmaxf(s[i][2], s[i][3]));
#pragma unroll
            for (int off = 1; off < 16; off <<= 1)
                tm[i] = fmaxf(tm[i], __shfl_xor_sync(0xffffffffu, tm[i], off));
        }

        float nm[4], corr[4], p[4][4], rst[4];
#pragma unroll
        for (int i = 0; i < 4; i++) {
            nm[i]   = fmaxf(rmax[i], tm[i]);
            corr[i] = __expf(rmax[i] - nm[i]);
            float ps = 0.f;
#pragma unroll
            for (int j = 0; j < 4; j++) {
                p[i][j] = __expf(s[i][j] - nm[i]);
                ps += p[i][j];
            }
            rst[i] = ps;
#pragma unroll
            for (int off = 1; off < 16; off <<= 1)
                rst[i] += __shfl_xor_sync(0xffffffffu, rst[i], off);
            rsum[i] = rsum[i] * corr[i] + rst[i];
            rmax[i] = nm[i];
#pragma unroll
            for (int j = 0; j < 8; j++) acc[i][j] *= corr[i];
        }

        // write P transposed: sPt[c][m]
#pragma unroll
        for (int j = 0; j < 4; j++)
#pragma unroll
            for (int i = 0; i < 4; i++)
                sPt[(j*16 + tx) * 65 + ty*4 + i] = p[i][j];

        __syncthreads();

        // O += P V
#pragma unroll 4
        for (int c = 0; c < 64; c++) {
            float pv[4];
#pragma unroll
            for (int i = 0; i < 4; i++) pv[i] = sPt[c*65 + ty*4 + i];
            float4 v0 = *(const float4*)(sV + c*132 + tx*8);
            float4 v1 = *(const float4*)(sV + c*132 + tx*8 + 4);
#pragma unroll
            for (int i = 0; i < 4; i++) {
                acc[i][0] += pv[i] * v0.x; acc[i][1] += pv[i] * v0.y;
                acc[i][2] += pv[i] * v0.z; acc[i][3] += pv[i] * v0.w;
                acc[i][4] += pv[i] * v1.x; acc[i][5] += pv[i] * v1.y;
                acc[i][6] += pv[i] * v1.z; acc[i][7] += pv[i] * v1.w;
            }
        }
    }

    // normalize + store into g_att
#pragma unroll
    for (int i = 0; i < 4; i++) {
        float inv = 1.0f / rsum[i];
        float* op = g_att + (size_t)(q0 + ty*4 + i) * D_DIM + h * HD + tx * 8;
        *(float4*)(op)     = make_float4(acc[i][0]*inv, acc[i][1]*inv,
                                         acc[i][2]*inv, acc[i][3]*inv);
        *(float4*)(op + 4) = make_float4(acc[i][4]*inv, acc[i][5]*inv,
                                         acc[i][6]*inv, acc[i][7]*inv);
    }
}

// ---------------------------------------------------------------------------
// Launch: x -> (Q,K,V) GEMMs -> RoPE -> flash attention -> output GEMM
// inputs: 0:x 1:cos 2:sin 3:mask 4:idx 5:cache_k 6:cache_v 7:wq 8:wk 9:wv 10:wo
// ---------------------------------------------------------------------------
extern "C" void kernel_launch(void* const* d_in, const int* in_sizes, int n_in,
                              void* d_out, int out_size)
{
    const float* x   = (const float*)d_in[0];
    const float* fc  = (const float*)d_in[1];
    const float* fs  = (const float*)d_in[2];
    const float* wq  = (const float*)d_in[7];
    const float* wk  = (const float*)d_in[8];
    const float* wv  = (const float*)d_in[9];
    const float* wo  = (const float*)d_in[10];
    float* out = (float*)d_out;

    cudaFuncSetAttribute(flash_kernel,
                         cudaFuncAttributeMaxDynamicSharedMemorySize,
                         FA_SMEM_BYTES);

    dim3 gQKV(D_DIM / BN, S_LEN / BM, 3);   // (32, 16, 3)
    qkv_gemm_kernel<<<gQKV, 256>>>(x, wq, wk, wv);

    int nPairs = S_LEN * NH * (HD / 2);
    rope_kernel<<<(nPairs + 255) / 256, 256>>>(fc, fs);

    flash_kernel<<<dim3(S_LEN / 64, NH), 256, FA_SMEM_BYTES>>>();

    dim3 gGemm(D_DIM / BN, S_LEN / BM);     // (32, 16)
    out_gemm_kernel<<<gGemm, 256>>>(wo, out);
}

// round 5
// speedup vs baseline: 2.2016x; 2.2016x over previous
#include <cuda_runtime.h>
#include <math.h>
#include <stdint.h>

#define S_LEN 2048
#define D_DIM 4096
#define NH    32
#define HD    128

// Scratch (allocation-free rule: __device__ globals)
__device__ float g_q[S_LEN * D_DIM];
__device__ float g_k[S_LEN * D_DIM];
__device__ float g_v[S_LEN * D_DIM];
__device__ float g_att[S_LEN * D_DIM];

// ---------------------------------------------------------------------------
// TF32 tensor-core GEMM (NT): C[M,N] = A[M,K] * B[N,K]^T, fp32 accum.
// CTA tile 128x128, 4 warps (2x2), warp tile 64x64 = 4(m16) x 8(n8) mma tiles.
// K staged 16 at a time, cp.async double buffer.
// Smem rows padded to 20 floats -> conflict-free 32-bit fragment loads.
// ---------------------------------------------------------------------------
#define TBM 128
#define TBN 128
#define TBK 16
#define TLD 20            // padded row length (floats); 20*4B = 80B, 16B aligned

__device__ __forceinline__ uint32_t f2tf32(float x) {
    uint32_t r;
    asm("cvt.rna.tf32.f32 %0, %1;" : "=r"(r) : "f"(x));
    return r;
}

__device__ __forceinline__ void mma_tf32(float* c, uint32_t a0, uint32_t a1,
                                         uint32_t a2, uint32_t a3,
                                         uint32_t b0, uint32_t b1) {
    asm volatile(
        "mma.sync.aligned.m16n8k8.row.col.f32.tf32.tf32.f32 "
        "{%0,%1,%2,%3}, {%4,%5,%6,%7}, {%8,%9}, {%0,%1,%2,%3};"
        : "+f"(c[0]), "+f"(c[1]), "+f"(c[2]), "+f"(c[3])
        : "r"(a0), "r"(a1), "r"(a2), "r"(a3), "r"(b0), "r"(b1));
}

__device__ __forceinline__ void cp16(uint32_t smem_dst, const float* gsrc) {
    asm volatile("cp.async.cg.shared.global [%0], [%1], 16;"
                 :: "r"(smem_dst), "l"(gsrc));
}

__device__ __forceinline__
void tgemm_body(const float* __restrict__ A, const float* __restrict__ B,
                float* __restrict__ C, int K, int N)
{
    __shared__ float As[2][TBM][TLD];
    __shared__ float Bs[2][TBN][TLD];

    const int tid  = threadIdx.x;
    const int lane = tid & 31;
    const int warp = tid >> 5;
    const int g    = lane >> 2;        // group id (row within 8)
    const int tg   = lane & 3;         // thread-in-group (k within 4)
    const int wm   = (warp >> 1) * 64;
    const int wn   = (warp & 1) * 64;
    const int mBase = blockIdx.y * TBM;
    const int nBase = blockIdx.x * TBN;

    // Loader: 512 float4 per operand per stage / 128 threads = 4 each.
    const float* gA[4];
    const float* gB[4];
    uint32_t offS[4];                  // byte offset within one buffer
    uint32_t sA0 = (uint32_t)__cvta_generic_to_shared(&As[0][0][0]);
    uint32_t sB0 = (uint32_t)__cvta_generic_to_shared(&Bs[0][0][0]);
    const uint32_t bufStride = TBM * TLD * 4;   // bytes per buffer

#pragma unroll
    for (int it = 0; it < 4; it++) {
        int idx = tid + it * 128;      // 0..511
        int row = idx >> 2;
        int kc  = idx & 3;
        gA[it]   = A + (size_t)(mBase + row) * K + kc * 4;
        gB[it]   = B + (size_t)(nBase + row) * K + kc * 4;
        offS[it] = (row * TLD + kc * 4) * 4;
    }

    float acc[4][8][4];
#pragma unroll
    for (int mi = 0; mi < 4; mi++)
#pragma unroll
        for (int ni = 0; ni < 8; ni++)
#pragma unroll
            for (int r = 0; r < 4; r++) acc[mi][ni][r] = 0.f;

    const int NSTG = K / TBK;          // 256

    // preload stage 0
#pragma unroll
    for (int it = 0; it < 4; it++) {
        cp16(sA0 + offS[it], gA[it]);
        cp16(sB0 + offS[it], gB[it]);
    }
    asm volatile("cp.async.commit_group;");

    for (int s = 0; s < NSTG; s++) {
        const int buf = s & 1;

        if (s + 1 < NSTG) {
            const int nb = buf ^ 1;
            const int k0 = (s + 1) * TBK;
#pragma unroll
            for (int it = 0; it < 4; it++) {
                cp16(sA0 + nb * bufStride + offS[it], gA[it] + k0);
                cp16(sB0 + nb * bufStride + offS[it], gB[it] + k0);
            }
            asm volatile("cp.async.commit_group;");
            asm volatile("cp.async.wait_group 1;");
        } else {
            asm volatile("cp.async.wait_group 0;");
        }
        __syncthreads();

#pragma unroll
        for (int ks = 0; ks < 2; ks++) {
            const int kb = ks * 8;
            uint32_t af[4][4], bf[8][2];
#pragma unroll
            for (int mi = 0; mi < 4; mi++) {
                const int r0 = wm + mi * 16;
                af[mi][0] = f2tf32(As[buf][r0 + g    ][kb + tg    ]);
                af[mi][1] = f2tf32(As[buf][r0 + 8 + g][kb + tg    ]);
                af[mi][2] = f2tf32(As[buf][r0 + g    ][kb + 4 + tg]);
                af[mi][3] = f2tf32(As[buf][r0 + 8 + g][kb + 4 + tg]);
            }
#pragma unroll
            for (int ni = 0; ni < 8; ni++) {
                const int c0 = wn + ni * 8;
                bf[ni][0] = f2tf32(Bs[buf][c0 + g][kb + tg    ]);
                bf[ni][1] = f2tf32(Bs[buf][c0 + g][kb + 4 + tg]);
            }
#pragma unroll
            for (int mi = 0; mi < 4; mi++)
#pragma unroll
                for (int ni = 0; ni < 8; ni++)
                    mma_tf32(acc[mi][ni], af[mi][0], af[mi][1], af[mi][2],
                             af[mi][3], bf[ni][0], bf[ni][1]);
        }
        __syncthreads();
    }

    // Epilogue: c0 (g, 2tg), c1 (g, 2tg+1), c2 (g+8, 2tg), c3 (g+8, 2tg+1)
#pragma unroll
    for (int mi = 0; mi < 4; mi++) {
#pragma unroll
        for (int ni = 0; ni < 8; ni++) {
            const int row = mBase + wm + mi * 16 + g;
            const int col = nBase + wn + ni * 8 + tg * 2;
            *(float2*)(C + (size_t)row * N + col) =
                make_float2(acc[mi][ni][0], acc[mi][ni][1]);
            *(float2*)(C + (size_t)(row + 8) * N + col) =
                make_float2(acc[mi][ni][2], acc[mi][ni][3]);
        }
    }
}

// QKV projections: one kernel, 3 GEMMs selected by blockIdx.z.
__global__ __launch_bounds__(128, 2)
void qkv_gemm_kernel(const float* __restrict__ x,
                     const float* __restrict__ wq,
                     const float* __restrict__ wk,
                     const float* __restrict__ wv)
{
    const float* B;
    float* C;
    if (blockIdx.z == 0)      { B = wq; C = g_q; }
    else if (blockIdx.z == 1) { B = wk; C = g_k; }
    else                      { B = wv; C = g_v; }
    tgemm_body(x, B, C, D_DIM, D_DIM);
}

__global__ __launch_bounds__(128, 2)
void out_gemm_kernel(const float* __restrict__ wo, float* __restrict__ out)
{
    tgemm_body(g_att, wo, out, D_DIM, D_DIM);
}

// ---------------------------------------------------------------------------
// RoPE (interleaved pairs), applied in-place to g_q and g_k.
// ---------------------------------------------------------------------------
__global__ void rope_kernel(const float* __restrict__ fcos,
                            const float* __restrict__ fsin)
{
    int idx = blockIdx.x * blockDim.x + threadIdx.x;
    if (idx >= S_LEN * NH * (HD / 2)) return;
    int s = idx >> 11;
    int r = idx & 2047;
    int h = r >> 6;
    int i = r & 63;

    float c  = fcos[s * 64 + i];
    float sn = fsin[s * 64 + i];
    size_t base = (size_t)s * D_DIM + h * HD + 2 * i;

    float qr = g_q[base], qi = g_q[base + 1];
    g_q[base]     = qr * c - qi * sn;
    g_q[base + 1] = qr * sn + qi * c;

    float kr = g_k[base], ki = g_k[base + 1];
    g_k[base]     = kr * c - ki * sn;
    g_k[base + 1] = kr * sn + ki * c;
}

// ---------------------------------------------------------------------------
// Flash attention (causal), fp32 — unchanged from the passing R3 version.
// smem: Qt[128][64] Kt[128][64] V[64][132] Pt[64][65]  = 113.25 KB dynamic
// ---------------------------------------------------------------------------
#define FA_SMEM_FLOATS (128*64 + 128*64 + 64*132 + 64*65)
#define FA_SMEM_BYTES  (FA_SMEM_FLOATS * 4)

__global__ __launch_bounds__(256, 1)
void flash_kernel()
{
    extern __shared__ float sm[];
    float* sQt = sm;                      // [128][64]
    float* sKt = sQt + 128 * 64;          // [128][64]
    float* sV  = sKt + 128 * 64;          // [64][132]
    float* sPt = sV  + 64 * 132;          // [64][65]

    const int h   = blockIdx.y;
    const int qt  = blockIdx.x;
    const int q0  = qt * 64;
    const int tid = threadIdx.x;
    const int tx  = tid & 15;
    const int ty  = tid >> 4;
    const float scale = 0.08838834764831845f;

    {
        int m  = tid >> 2;
        int vb = tid & 3;
        const float* qp = g_q + (size_t)(q0 + m) * D_DIM + h * HD;
#pragma unroll
        for (int vv = vb; vv < 32; vv += 4) {
            float4 t = *(const float4*)(qp + vv * 4);
            int d = vv * 4;
            sQt[(d+0)*64 + m] = t.x; sQt[(d+1)*64 + m] = t.y;
            sQt[(d+2)*64 + m] = t.z; sQt[(d+3)*64 + m] = t.w;
        }
    }

    float acc[4][8];
#pragma unroll
    for (int i = 0; i < 4; i++)
#pragma unroll
        for (int j = 0; j < 8; j++) acc[i][j] = 0.f;

    float rmax[4] = {-INFINITY, -INFINITY, -INFINITY, -INFINITY};
    float rsum[4] = {0.f, 0.f, 0.f, 0.f};

    for (int jt = 0; jt <= qt; jt++) {
        const int k0 = jt * 64;

        __syncthreads();

        {
            int m  = tid >> 2;
            int vb = tid & 3;
            const float* kp = g_k + (size_t)(k0 + m) * D_DIM + h * HD;
            const float* vp = g_v + (size_t)(k0 + m) * D_DIM + h * HD;
#pragma unroll
            for (int vv = vb; vv < 32; vv += 4) {
                float4 t = *(const float4*)(kp + vv * 4);
                int d = vv * 4;
                sKt[(d+0)*64 + m] = t.x; sKt[(d+1)*64 + m] = t.y;
                sKt[(d+2)*64 + m] = t.z; sKt[(d+3)*64 + m] = t.w;
                *(float4*)(sV + m * 132 + vv * 4) = *(const float4*)(vp + vv * 4);
            }
        }
        __syncthreads();

        float s[4][4];
#pragma unroll
        for (int i = 0; i < 4; i++)
#pragma unroll
            for (int j = 0; j < 4; j++) s[i][j] = 0.f;

#pragma unroll 8
        for (int d = 0; d < 128; d++) {
            float qa[4], kb[4];
#pragma unroll
            for (int i = 0; i < 4; i++) qa[i] = sQt[d*64 + ty*4 + i];
#pragma unroll
            for (int j = 0; j < 4; j++) kb[j] = sKt[d*64 + j*16 + tx];
#pragma unroll
            for (int i = 0; i < 4; i++)
#pragma unroll
                for (int j = 0; j < 4; j++)
                    s[i][j] += qa[i] * kb[j];
        }

        if (jt == qt) {
#pragma unroll
            for (int i = 0; i < 4; i++)
#pragma unroll
                for (int j = 0; j < 4; j++) {
                    int col = j * 16 + tx;
                    int row = ty * 4 + i;
                    s[i][j] = (col > row) ? -1.0e9f : s[i][j] * scale;
                }
        } else {
#pragma unroll
            for (int i = 0; i < 4; i++)
#pragma unroll
                for (int j = 0; j < 4; j++) s[i][j] *= scale;
        }

        float tm[4];
#pragma unroll
        for (int i = 0; i < 4; i++) {
            tm[i] = fmaxf(fmaxf(s[i][0], s[i][1]), fmaxf(s[i][2], s[i][3]));
#pragma unroll
            for (int off = 1; off < 16; off <<= 1)
                tm[i] = fmaxf(tm[i], __shfl_xor_sync(0xffffffffu, tm[i], off));
        }

        float nm[4], corr[4], p[4][4], rst[4];
#pragma unroll
        for (int i = 0; i < 4; i++) {
            nm[i]   = fmaxf(rmax[i], tm[i]);
            corr[i] = __expf(rmax[i] - nm[i]);
            float ps = 0.f;
#pragma unroll
            for (int j = 0; j < 4; j++) {
                p[i][j] = __expf(s[i][j] - nm[i]);
                ps += p[i][j];
            }
            rst[i] = ps;
#pragma unroll
            for (int off = 1; off < 16; off <<= 1)
                rst[i] += __shfl_xor_sync(0xffffffffu, rst[i], off);
            rsum[i] = rsum[i] * corr[i] + rst[i];
            rmax[i] = nm[i];
#pragma unroll
            for (int j = 0; j < 8; j++) acc[i][j] *= corr[i];
        }

#pragma unroll
        for (int j = 0; j < 4; j++)
#pragma unroll
            for (int i = 0; i < 4; i++)
                sPt[(j*16 + tx) * 65 + ty*4 + i] = p[i][j];

        __syncthreads();

#pragma unroll 4
        for (int c = 0; c < 64; c++) {
            float pv[4];
#pragma unroll
            for (int i = 0; i < 4; i++) pv[i] = sPt[c*65 + ty*4 + i];
            float4 v0 = *(const float4*)(sV + c*132 + tx*8);
            float4 v1 = *(const float4*)(sV + c*132 + tx*8 + 4);
#pragma unroll
            for (int i = 0; i < 4; i++) {
                acc[i][0] += pv[i] * v0.x; acc[i][1] += pv[i] * v0.y;
                acc[i][2] += pv[i] * v0.z; acc[i][3] += pv[i] * v0.w;
                acc[i][4] += pv[i] * v1.x; acc[i][5] += pv[i] * v1.y;
                acc[i][6] += pv[i] * v1.z; acc[i][7] += pv[i] * v1.w;
            }
        }
    }

#pragma unroll
    for (int i = 0; i < 4; i++) {
        float inv = 1.0f / rsum[i];
        float* op = g_att + (size_t)(q0 + ty*4 + i) * D_DIM + h * HD + tx * 8;
        *(float4*)(op)     = make_float4(acc[i][0]*inv, acc[i][1]*inv,
                                         acc[i][2]*inv, acc[i][3]*inv);
        *(float4*)(op + 4) = make_float4(acc[i][4]*inv, acc[i][5]*inv,
                                         acc[i][6]*inv, acc[i][7]*inv);
    }
}

// ---------------------------------------------------------------------------
// inputs: 0:x 1:cos 2:sin 3:mask 4:idx 5:cache_k 6:cache_v 7:wq 8:wk 9:wv 10:wo
// ---------------------------------------------------------------------------
extern "C" void kernel_launch(void* const* d_in, const int* in_sizes, int n_in,
                              void* d_out, int out_size)
{
    const float* x   = (const float*)d_in[0];
    const float* fc  = (const float*)d_in[1];
    const float* fs  = (const float*)d_in[2];
    const float* wq  = (const float*)d_in[7];
    const float* wk  = (const float*)d_in[8];
    const float* wv  = (const float*)d_in[9];
    const float* wo  = (const float*)d_in[10];
    float* out = (float*)d_out;

    cudaFuncSetAttribute(flash_kernel,
                         cudaFuncAttributeMaxDynamicSharedMemorySize,
                         FA_SMEM_BYTES);

    dim3 gQKV(D_DIM / TBN, S_LEN / TBM, 3);   // (32, 16, 3)
    qkv_gemm_kernel<<<gQKV, 128>>>(x, wq, wk, wv);

    int nPairs = S_LEN * NH * (HD / 2);
    rope_kernel<<<(nPairs + 255) / 256, 256>>>(fc, fs);

    flash_kernel<<<dim3(S_LEN / 64, NH), 256, FA_SMEM_BYTES>>>();

    dim3 gGemm(D_DIM / TBN, S_LEN / TBM);     // (32, 16)
    out_gemm_kernel<<<gGemm, 128>>>(wo, out);
}

// round 6
// speedup vs baseline: 2.2856x; 1.0382x over previous
#include <cuda_runtime.h>
#include <math.h>
#include <stdint.h>

#define S_LEN 2048
#define D_DIM 4096
#define NH    32
#define HD    128

// Scratch (allocation-free rule: __device__ globals)
__device__ float g_q[S_LEN * D_DIM];
__device__ float g_k[S_LEN * D_DIM];
__device__ float g_v[S_LEN * D_DIM];
__device__ float g_att[S_LEN * D_DIM];

// ---------------------------------------------------------------------------
// TF32 tensor-core GEMM (NT): C[M,N] = A[M,K] * B[N,K]^T, fp32 accum.
// CTA tile 128x128, 8 warps (2x4), warp tile 64x32 = 4(m16) x 4(n8) mma tiles.
// 64 accum regs/thread -> 2 CTAs/SM (16 warps) for latency hiding.
// K staged 16 at a time, cp.async double buffer, smem rows padded to 20.
// ---------------------------------------------------------------------------
#define TBM 128
#define TBN 128
#define TBK 16
#define TLD 20            // padded row length (floats)

__device__ __forceinline__ uint32_t f2tf32(float x) {
    uint32_t r;
    asm("cvt.rna.tf32.f32 %0, %1;" : "=r"(r) : "f"(x));
    return r;
}

__device__ __forceinline__ void mma_tf32(float* c, uint32_t a0, uint32_t a1,
                                         uint32_t a2, uint32_t a3,
                                         uint32_t b0, uint32_t b1) {
    asm volatile(
        "mma.sync.aligned.m16n8k8.row.col.f32.tf32.tf32.f32 "
        "{%0,%1,%2,%3}, {%4,%5,%6,%7}, {%8,%9}, {%0,%1,%2,%3};"
        : "+f"(c[0]), "+f"(c[1]), "+f"(c[2]), "+f"(c[3])
        : "r"(a0), "r"(a1), "r"(a2), "r"(a3), "r"(b0), "r"(b1));
}

__device__ __forceinline__ void cp16(uint32_t smem_dst, const float* gsrc) {
    asm volatile("cp.async.cg.shared.global [%0], [%1], 16;"
                 :: "r"(smem_dst), "l"(gsrc));
}

__device__ __forceinline__
void tgemm_body(const float* __restrict__ A, const float* __restrict__ B,
                float* __restrict__ C, int K, int N)
{
    __shared__ float As[2][TBM][TLD];
    __shared__ float Bs[2][TBN][TLD];

    const int tid  = threadIdx.x;
    const int lane = tid & 31;
    const int warp = tid >> 5;        // 0..7
    const int g    = lane >> 2;       // row-in-8
    const int tg   = lane & 3;        // k-in-4
    const int wm   = (warp >> 2) * 64;   // 2 warp rows
    const int wn   = (warp & 3) * 32;    // 4 warp cols
    const int mBase = blockIdx.y * TBM;
    const int nBase = blockIdx.x * TBN;

    // Loader: 512 float4 per operand per stage / 256 threads = 2 each.
    const float* gA[2];
    const float* gB[2];
    uint32_t offS[2];                  // byte offset within one buffer
    uint32_t sA0 = (uint32_t)__cvta_generic_to_shared(&As[0][0][0]);
    uint32_t sB0 = (uint32_t)__cvta_generic_to_shared(&Bs[0][0][0]);
    const uint32_t bufStride = TBM * TLD * 4;   // bytes per buffer

#pragma unroll
    for (int it = 0; it < 2; it++) {
        int idx = tid + it * 256;      // 0..511
        int row = idx >> 2;
        int kc  = idx & 3;
        gA[it]   = A + (size_t)(mBase + row) * K + kc * 4;
        gB[it]   = B + (size_t)(nBase + row) * K + kc * 4;
        offS[it] = (row * TLD + kc * 4) * 4;
    }

    float acc[4][4][4];
#pragma unroll
    for (int mi = 0; mi < 4; mi++)
#pragma unroll
        for (int ni = 0; ni < 4; ni++)
#pragma unroll
            for (int r = 0; r < 4; r++) acc[mi][ni][r] = 0.f;

    const int NSTG = K / TBK;

    // preload stage 0
#pragma unroll
    for (int it = 0; it < 2; it++) {
        cp16(sA0 + offS[it], gA[it]);
        cp16(sB0 + offS[it], gB[it]);
    }
    asm volatile("cp.async.commit_group;");

    for (int s = 0; s < NSTG; s++) {
        const int buf = s & 1;

        if (s + 1 < NSTG) {
            const int nb = buf ^ 1;
            const int k0 = (s + 1) * TBK;
#pragma unroll
            for (int it = 0; it < 2; it++) {
                cp16(sA0 + nb * bufStride + offS[it], gA[it] + k0);
                cp16(sB0 + nb * bufStride + offS[it], gB[it] + k0);
            }
            asm volatile("cp.async.commit_group;");
            asm volatile("cp.async.wait_group 1;");
        } else {
            asm volatile("cp.async.wait_group 0;");
        }
        __syncthreads();

#pragma unroll
        for (int ks = 0; ks < 2; ks++) {
            const int kb = ks * 8;
            uint32_t af[4][4], bf[4][2];
#pragma unroll
            for (int mi = 0; mi < 4; mi++) {
                const int r0 = wm + mi * 16;
                af[mi][0] = f2tf32(As[buf][r0 + g    ][kb + tg    ]);
                af[mi][1] = f2tf32(As[buf][r0 + 8 + g][kb + tg    ]);
                af[mi][2] = f2tf32(As[buf][r0 + g    ][kb + 4 + tg]);
                af[mi][3] = f2tf32(As[buf][r0 + 8 + g][kb + 4 + tg]);
            }
#pragma unroll
            for (int ni = 0; ni < 4; ni++) {
                const int c0 = wn + ni * 8;
                bf[ni][0] = f2tf32(Bs[buf][c0 + g][kb + tg    ]);
                bf[ni][1] = f2tf32(Bs[buf][c0 + g][kb + 4 + tg]);
            }
#pragma unroll
            for (int mi = 0; mi < 4; mi++)
#pragma unroll
                for (int ni = 0; ni < 4; ni++)
                    mma_tf32(acc[mi][ni], af[mi][0], af[mi][1], af[mi][2],
                             af[mi][3], bf[ni][0], bf[ni][1]);
        }
        __syncthreads();
    }

    // Epilogue
#pragma unroll
    for (int mi = 0; mi < 4; mi++) {
#pragma unroll
        for (int ni = 0; ni < 4; ni++) {
            const int row = mBase + wm + mi * 16 + g;
            const int col = nBase + wn + ni * 8 + tg * 2;
            *(float2*)(C + (size_t)row * N + col) =
                make_float2(acc[mi][ni][0], acc[mi][ni][1]);
            *(float2*)(C + (size_t)(row + 8) * N + col) =
                make_float2(acc[mi][ni][2], acc[mi][ni][3]);
        }
    }
}

// QKV projections: one kernel, 3 GEMMs selected by blockIdx.z.
__global__ __launch_bounds__(256, 2)
void qkv_gemm_kernel(const float* __restrict__ x,
                     const float* __restrict__ wq,
                     const float* __restrict__ wk,
                     const float* __restrict__ wv)
{
    const float* B;
    float* C;
    if (blockIdx.z == 0)      { B = wq; C = g_q; }
    else if (blockIdx.z == 1) { B = wk; C = g_k; }
    else                      { B = wv; C = g_v; }
    tgemm_body(x, B, C, D_DIM, D_DIM);
}

__global__ __launch_bounds__(256, 2)
void out_gemm_kernel(const float* __restrict__ wo, float* __restrict__ out)
{
    tgemm_body(g_att, wo, out, D_DIM, D_DIM);
}

// ---------------------------------------------------------------------------
// RoPE (interleaved pairs), applied in-place to g_q and g_k.
// ---------------------------------------------------------------------------
__global__ void rope_kernel(const float* __restrict__ fcos,
                            const float* __restrict__ fsin)
{
    int idx = blockIdx.x * blockDim.x + threadIdx.x;
    if (idx >= S_LEN * NH * (HD / 2)) return;
    int s = idx >> 11;
    int r = idx & 2047;
    int h = r >> 6;
    int i = r & 63;

    float c  = fcos[s * 64 + i];
    float sn = fsin[s * 64 + i];
    size_t base = (size_t)s * D_DIM + h * HD + 2 * i;

    float qr = g_q[base], qi = g_q[base + 1];
    g_q[base]     = qr * c - qi * sn;
    g_q[base + 1] = qr * sn + qi * c;

    float kr = g_k[base], ki = g_k[base + 1];
    g_k[base]     = kr * c - ki * sn;
    g_k[base + 1] = kr * sn + ki * c;
}

// ---------------------------------------------------------------------------
// Flash attention (causal), fp32 — unchanged from the passing version.
// smem: Qt[128][64] Kt[128][64] V[64][132] Pt[64][65]  = 113.25 KB dynamic
// ---------------------------------------------------------------------------
#define FA_SMEM_FLOATS (128*64 + 128*64 + 64*132 + 64*65)
#define FA_SMEM_BYTES  (FA_SMEM_FLOATS * 4)

__global__ __launch_bounds__(256, 1)
void flash_kernel()
{
    extern __shared__ float sm[];
    float* sQt = sm;                      // [128][64]
    float* sKt = sQt + 128 * 64;          // [128][64]
    float* sV  = sKt + 128 * 64;          // [64][132]
    float* sPt = sV  + 64 * 132;          // [64][65]

    const int h   = blockIdx.y;
    const int qt  = blockIdx.x;
    const int q0  = qt * 64;
    const int tid = threadIdx.x;
    const int tx  = tid & 15;
    const int ty  = tid >> 4;
    const float scale = 0.08838834764831845f;

    {
        int m  = tid >> 2;
        int vb = tid & 3;
        const float* qp = g_q + (size_t)(q0 + m) * D_DIM + h * HD;
#pragma unroll
        for (int vv = vb; vv < 32; vv += 4) {
            float4 t = *(const float4*)(qp + vv * 4);
            int d = vv * 4;
            sQt[(d+0)*64 + m] = t.x; sQt[(d+1)*64 + m] = t.y;
            sQt[(d+2)*64 + m] = t.z; sQt[(d+3)*64 + m] = t.w;
        }
    }

    float acc[4][8];
#pragma unroll
    for (int i = 0; i < 4; i++)
#pragma unroll
        for (int j = 0; j < 8; j++) acc[i][j] = 0.f;

    float rmax[4] = {-INFINITY, -INFINITY, -INFINITY, -INFINITY};
    float rsum[4] = {0.f, 0.f, 0.f, 0.f};

    for (int jt = 0; jt <= qt; jt++) {
        const int k0 = jt * 64;

        __syncthreads();

        {
            int m  = tid >> 2;
            int vb = tid & 3;
            const float* kp = g_k + (size_t)(k0 + m) * D_DIM + h * HD;
            const float* vp = g_v + (size_t)(k0 + m) * D_DIM + h * HD;
#pragma unroll
            for (int vv = vb; vv < 32; vv += 4) {
                float4 t = *(const float4*)(kp + vv * 4);
                int d = vv * 4;
                sKt[(d+0)*64 + m] = t.x; sKt[(d+1)*64 + m] = t.y;
                sKt[(d+2)*64 + m] = t.z; sKt[(d+3)*64 + m] = t.w;
                *(float4*)(sV + m * 132 + vv * 4) = *(const float4*)(vp + vv * 4);
            }
        }
        __syncthreads();

        float s[4][4];
#pragma unroll
        for (int i = 0; i < 4; i++)
#pragma unroll
            for (int j = 0; j < 4; j++) s[i][j] = 0.f;

#pragma unroll 8
        for (int d = 0; d < 128; d++) {
            float qa[4], kb[4];
#pragma unroll
            for (int i = 0; i < 4; i++) qa[i] = sQt[d*64 + ty*4 + i];
#pragma unroll
            for (int j = 0; j < 4; j++) kb[j] = sKt[d*64 + j*16 + tx];
#pragma unroll
            for (int i = 0; i < 4; i++)
#pragma unroll
                for (int j = 0; j < 4; j++)
                    s[i][j] += qa[i] * kb[j];
        }

        if (jt == qt) {
#pragma unroll
            for (int i = 0; i < 4; i++)
#pragma unroll
                for (int j = 0; j < 4; j++) {
                    int col = j * 16 + tx;
                    int row = ty * 4 + i;
                    s[i][j] = (col > row) ? -1.0e9f : s[i][j] * scale;
                }
        } else {
#pragma unroll
            for (int i = 0; i < 4; i++)
#pragma unroll
                for (int j = 0; j < 4; j++) s[i][j] *= scale;
        }

        float tm[4];
#pragma unroll
        for (int i = 0; i < 4; i++) {
            tm[i] = fmaxf(fmaxf(s[i][0], s[i][1]), fmaxf(s[i][2], s[i][3]));
#pragma unroll
            for (int off = 1; off < 16; off <<= 1)
                tm[i] = fmaxf(tm[i], __shfl_xor_sync(0xffffffffu, tm[i], off));
        }

        float nm[4], corr[4], p[4][4], rst[4];
#pragma unroll
        for (int i = 0; i < 4; i++) {
            nm[i]   = fmaxf(rmax[i], tm[i]);
            corr[i] = __expf(rmax[i] - nm[i]);
            float ps = 0.f;
#pragma unroll
            for (int j = 0; j < 4; j++) {
                p[i][j] = __expf(s[i][j] - nm[i]);
                ps += p[i][j];
            }
            rst[i] = ps;
#pragma unroll
            for (int off = 1; off < 16; off <<= 1)
                rst[i] += __shfl_xor_sync(0xffffffffu, rst[i], off);
            rsum[i] = rsum[i] * corr[i] + rst[i];
            rmax[i] = nm[i];
#pragma unroll
            for (int j = 0; j < 8; j++) acc[i][j] *= corr[i];
        }

#pragma unroll
        for (int j = 0; j < 4; j++)
#pragma unroll
            for (int i = 0; i < 4; i++)
                sPt[(j*16 + tx) * 65 + ty*4 + i] = p[i][j];

        __syncthreads();

#pragma unroll 4
        for (int c = 0; c < 64; c++) {
            float pv[4];
#pragma unroll
            for (int i = 0; i < 4; i++) pv[i] = sPt[c*65 + ty*4 + i];
            float4 v0 = *(const float4*)(sV + c*132 + tx*8);
            float4 v1 = *(const float4*)(sV + c*132 + tx*8 + 4);
#pragma unroll
            for (int i = 0; i < 4; i++) {
                acc[i][0] += pv[i] * v0.x; acc[i][1] += pv[i] * v0.y;
                acc[i][2] += pv[i] * v0.z; acc[i][3] += pv[i] * v0.w;
                acc[i][4] += pv[i] * v1.x; acc[i][5] += pv[i] * v1.y;
                acc[i][6] += pv[i] * v1.z; acc[i][7] += pv[i] * v1.w;
            }
        }
    }

#pragma unroll
    for (int i = 0; i < 4; i++) {
        float inv = 1.0f / rsum[i];
        float* op = g_att + (size_t)(q0 + ty*4 + i) * D_DIM + h * HD + tx * 8;
        *(float4*)(op)     = make_float4(acc[i][0]*inv, acc[i][1]*inv,
                                         acc[i][2]*inv, acc[i][3]*inv);
        *(float4*)(op + 4) = make_float4(acc[i][4]*inv, acc[i][5]*inv,
                                         acc[i][6]*inv, acc[i][7]*inv);
    }
}

// ---------------------------------------------------------------------------
// inputs: 0:x 1:cos 2:sin 3:mask 4:idx 5:cache_k 6:cache_v 7:wq 8:wk 9:wv 10:wo
// ---------------------------------------------------------------------------
extern "C" void kernel_launch(void* const* d_in, const int* in_sizes, int n_in,
                              void* d_out, int out_size)
{
    const float* x   = (const float*)d_in[0];
    const float* fc  = (const float*)d_in[1];
    const float* fs  = (const float*)d_in[2];
    const float* wq  = (const float*)d_in[7];
    const float* wk  = (const float*)d_in[8];
    const float* wv  = (const float*)d_in[9];
    const float* wo  = (const float*)d_in[10];
    float* out = (float*)d_out;

    cudaFuncSetAttribute(flash_kernel,
                         cudaFuncAttributeMaxDynamicSharedMemorySize,
                         FA_SMEM_BYTES);

    dim3 gQKV(D_DIM / TBN, S_LEN / TBM, 3);   // (32, 16, 3)
    qkv_gemm_kernel<<<gQKV, 256>>>(x, wq, wk, wv);

    int nPairs = S_LEN * NH * (HD / 2);
    rope_kernel<<<(nPairs + 255) / 256, 256>>>(fc, fs);

    flash_kernel<<<dim3(S_LEN / 64, NH), 256, FA_SMEM_BYTES>>>();

    dim3 gGemm(D_DIM / TBN, S_LEN / TBM);     // (32, 16)
    out_gemm_kernel<<<gGemm, 256>>>(wo, out);
}

// round 7
// speedup vs baseline: 2.4415x; 1.0682x over previous
#include <cuda_runtime.h>
#include <math.h>
#include <stdint.h>

#define S_LEN 2048
#define D_DIM 4096
#define NH    32
#define HD    128

// Scratch (allocation-free rule: __device__ globals)
__device__ float g_q  [S_LEN * D_DIM];
__device__ float g_k  [S_LEN * D_DIM];
__device__ float g_v  [S_LEN * D_DIM];
__device__ float g_att[S_LEN * D_DIM];
// tf32-rounded, k-permuted operand copies
__device__ float g_xp  [S_LEN * D_DIM];
__device__ float g_attp[S_LEN * D_DIM];
__device__ float g_wqp [D_DIM * D_DIM];
__device__ float g_wkp [D_DIM * D_DIM];
__device__ float g_wvp [D_DIM * D_DIM];
__device__ float g_wop [D_DIM * D_DIM];

__device__ __forceinline__ float f2tf32f(float x) {
    uint32_t r;
    asm("cvt.rna.tf32.f32 %0, %1;" : "=r"(r) : "f"(x));
    return __uint_as_float(r);
}

// ---------------------------------------------------------------------------
// Prepass: round to tf32 and permute k within each 8-block:
// out slot p holds k = (p&1)*4 + (p>>1)  (i.e. {k0,k4,k1,k5, k2,k6,k3,k7})
// ---------------------------------------------------------------------------
__global__ void tf32_permute_kernel(const float* __restrict__ src,
                                    float* __restrict__ dst, int n8)
{
    int i = blockIdx.x * blockDim.x + threadIdx.x;
    if (i >= n8) return;
    const float4* s = (const float4*)(src + (size_t)i * 8);
    float4 v0 = s[0], v1 = s[1];
    float r0 = f2tf32f(v0.x), r1 = f2tf32f(v0.y);
    float r2 = f2tf32f(v0.z), r3 = f2tf32f(v0.w);
    float r4 = f2tf32f(v1.x), r5 = f2tf32f(v1.y);
    float r6 = f2tf32f(v1.z), r7 = f2tf32f(v1.w);
    float4* d = (float4*)(dst + (size_t)i * 8);
    d[0] = make_float4(r0, r4, r1, r5);
    d[1] = make_float4(r2, r6, r3, r7);
}

// ---------------------------------------------------------------------------
// TF32 tensor-core GEMM (NT) on pre-rounded, k-permuted operands.
// CTA 128x128, 8 warps (2x4), warp tile 64x32 (4x4 m16n8k8), fp32 accum.
// 3-stage cp.async pipeline; smem rows padded to TLD=24 floats ->
// conflict-free LDS.64 fragment loads (pairs k=tg / k=tg+4 adjacent).
// ---------------------------------------------------------------------------
#define TBM 128
#define TBN 128
#define TBK 16
#define TLD 24
#define NSTAGE 3
#define GEMM_SMEM (NSTAGE * 2 * TBM * TLD * 4)   // 73728 bytes

__device__ __forceinline__ void mma_tf32(float* c, uint32_t a0, uint32_t a1,
                                         uint32_t a2, uint32_t a3,
                                         uint32_t b0, uint32_t b1) {
    asm volatile(
        "mma.sync.aligned.m16n8k8.row.col.f32.tf32.tf32.f32 "
        "{%0,%1,%2,%3}, {%4,%5,%6,%7}, {%8,%9}, {%0,%1,%2,%3};"
        : "+f"(c[0]), "+f"(c[1]), "+f"(c[2]), "+f"(c[3])
        : "r"(a0), "r"(a1), "r"(a2), "r"(a3), "r"(b0), "r"(b1));
}

__device__ __forceinline__ void cp16(uint32_t smem_dst, const float* gsrc) {
    asm volatile("cp.async.cg.shared.global [%0], [%1], 16;"
                 :: "r"(smem_dst), "l"(gsrc));
}

__device__ __forceinline__
void tgemm_body(const float* __restrict__ A, const float* __restrict__ B,
                float* __restrict__ C, int K, int N)
{
    extern __shared__ float smem[];
    float* Asm = smem;                          // [NSTAGE][TBM][TLD]
    float* Bsm = smem + NSTAGE * TBM * TLD;     // [NSTAGE][TBN][TLD]

    const int tid  = threadIdx.x;
    const int lane = tid & 31;
    const int warp = tid >> 5;           // 0..7
    const int g    = lane >> 2;          // row-in-8
    const int tg   = lane & 3;           // k-in-4
    const int wm   = (warp >> 2) * 64;
    const int wn   = (warp & 3) * 32;
    const int mBase = blockIdx.y * TBM;
    const int nBase = blockIdx.x * TBN;

    // Loader: 512 float4 per operand per stage / 256 threads = 2 each.
    const float* gA[2];
    const float* gB[2];
    uint32_t offS[2];
    uint32_t sA0 = (uint32_t)__cvta_generic_to_shared(Asm);
    uint32_t sB0 = (uint32_t)__cvta_generic_to_shared(Bsm);
    const uint32_t bufStride = TBM * TLD * 4;   // bytes per stage buffer

#pragma unroll
    for (int it = 0; it < 2; it++) {
        int idx = tid + it * 256;        // 0..511
        int row = idx >> 2;
        int kc  = idx & 3;
        gA[it]   = A + (size_t)(mBase + row) * K + kc * 4;
        gB[it]   = B + (size_t)(nBase + row) * K + kc * 4;
        offS[it] = (row * TLD + kc * 4) * 4;
    }

    float acc[4][4][4];
#pragma unroll
    for (int mi = 0; mi < 4; mi++)
#pragma unroll
        for (int ni = 0; ni < 4; ni++)
#pragma unroll
            for (int r = 0; r < 4; r++) acc[mi][ni][r] = 0.f;

    const int NSTG = K / TBK;

    // prologue: stages 0 and 1
#pragma unroll
    for (int ps = 0; ps < NSTAGE - 1; ps++) {
        const uint32_t bo = ps * bufStride;
        const int k0 = ps * TBK;
#pragma unroll
        for (int it = 0; it < 2; it++) {
            cp16(sA0 + bo + offS[it], gA[it] + k0);
            cp16(sB0 + bo + offS[it], gB[it] + k0);
        }
        asm volatile("cp.async.commit_group;");
    }

    for (int s = 0; s < NSTG; s++) {
        if (s == NSTG - 1)
            asm volatile("cp.async.wait_group 0;");
        else
            asm volatile("cp.async.wait_group %0;" :: "n"(NSTAGE - 2));
        __syncthreads();

        // prefetch stage s+2 into its (now free) buffer
        if (s + NSTAGE - 1 < NSTG) {
            const uint32_t bo = ((s + NSTAGE - 1) % NSTAGE) * bufStride;
            const int k0 = (s + NSTAGE - 1) * TBK;
#pragma unroll
            for (int it = 0; it < 2; it++) {
                cp16(sA0 + bo + offS[it], gA[it] + k0);
                cp16(sB0 + bo + offS[it], gB[it] + k0);
            }
            asm volatile("cp.async.commit_group;");
        }

        const float* Ab = Asm + (s % NSTAGE) * TBM * TLD;
        const float* Bb = Bsm + (s % NSTAGE) * TBN * TLD;

#pragma unroll
        for (int ks = 0; ks < 2; ks++) {
            const int kb = ks * 8;       // permuted: col kb+2tg -> (k=tg, k=tg+4)
            uint2 a[4][2], b[4];
#pragma unroll
            for (int mi = 0; mi < 4; mi++) {
                const int r0 = wm + mi * 16;
                a[mi][0] = *(const uint2*)(Ab + (r0 + g    ) * TLD + kb + 2 * tg);
                a[mi][1] = *(const uint2*)(Ab + (r0 + 8 + g) * TLD + kb + 2 * tg);
            }
#pragma unroll
            for (int ni = 0; ni < 4; ni++) {
                const int c0 = wn + ni * 8;
                b[ni] = *(const uint2*)(Bb + (c0 + g) * TLD + kb + 2 * tg);
            }
#pragma unroll
            for (int mi = 0; mi < 4; mi++)
#pragma unroll
                for (int ni = 0; ni < 4; ni++)
                    mma_tf32(acc[mi][ni],
                             a[mi][0].x, a[mi][1].x, a[mi][0].y, a[mi][1].y,
                             b[ni].x, b[ni].y);
        }
    }

    // Epilogue
#pragma unroll
    for (int mi = 0; mi < 4; mi++) {
#pragma unroll
        for (int ni = 0; ni < 4; ni++) {
            const int row = mBase + wm + mi * 16 + g;
            const int col = nBase + wn + ni * 8 + tg * 2;
            *(float2*)(C + (size_t)row * N + col) =
                make_float2(acc[mi][ni][0], acc[mi][ni][1]);
            *(float2*)(C + (size_t)(row + 8) * N + col) =
                make_float2(acc[mi][ni][2], acc[mi][ni][3]);
        }
    }
}

// QKV projections: one kernel, 3 GEMMs selected by blockIdx.z.
__global__ __launch_bounds__(256, 2)
void qkv_gemm_kernel()
{
    const float* B;
    float* C;
    if (blockIdx.z == 0)      { B = g_wqp; C = g_q; }
    else if (blockIdx.z == 1) { B = g_wkp; C = g_k; }
    else                      { B = g_wvp; C = g_v; }
    tgemm_body(g_xp, B, C, D_DIM, D_DIM);
}

__global__ __launch_bounds__(256, 2)
void out_gemm_kernel(float* __restrict__ out)
{
    tgemm_body(g_attp, g_wop, out, D_DIM, D_DIM);
}

// ---------------------------------------------------------------------------
// RoPE (interleaved pairs), applied in-place to g_q and g_k.
// ---------------------------------------------------------------------------
__global__ void rope_kernel(const float* __restrict__ fcos,
                            const float* __restrict__ fsin)
{
    int idx = blockIdx.x * blockDim.x + threadIdx.x;
    if (idx >= S_LEN * NH * (HD / 2)) return;
    int s = idx >> 11;
    int r = idx & 2047;
    int h = r >> 6;
    int i = r & 63;

    float c  = fcos[s * 64 + i];
    float sn = fsin[s * 64 + i];
    size_t base = (size_t)s * D_DIM + h * HD + 2 * i;

    float qr = g_q[base], qi = g_q[base + 1];
    g_q[base]     = qr * c - qi * sn;
    g_q[base + 1] = qr * sn + qi * c;

    float kr = g_k[base], ki = g_k[base + 1];
    g_k[base]     = kr * c - ki * sn;
    g_k[base + 1] = kr * sn + ki * c;
}

// ---------------------------------------------------------------------------
// Flash attention (causal), fp32 — unchanged from the passing version.
// smem: Qt[128][64] Kt[128][64] V[64][132] Pt[64][65]  = 113.25 KB dynamic
// ---------------------------------------------------------------------------
#define FA_SMEM_FLOATS (128*64 + 128*64 + 64*132 + 64*65)
#define FA_SMEM_BYTES  (FA_SMEM_FLOATS * 4)

__global__ __launch_bounds__(256, 1)
void flash_kernel()
{
    extern __shared__ float sm[];
    float* sQt = sm;                      // [128][64]
    float* sKt = sQt + 128 * 64;          // [128][64]
    float* sV  = sKt + 128 * 64;          // [64][132]
    float* sPt = sV  + 64 * 132;          // [64][65]

    const int h   = blockIdx.y;
    const int qt  = blockIdx.x;
    const int q0  = qt * 64;
    const int tid = threadIdx.x;
    const int tx  = tid & 15;
    const int ty  = tid >> 4;
    const float scale = 0.08838834764831845f;

    {
        int m  = tid >> 2;
        int vb = tid & 3;
        const float* qp = g_q + (size_t)(q0 + m) * D_DIM + h * HD;
#pragma unroll
        for (int vv = vb; vv < 32; vv += 4) {
            float4 t = *(const float4*)(qp + vv * 4);
            int d = vv * 4;
            sQt[(d+0)*64 + m] = t.x; sQt[(d+1)*64 + m] = t.y;
            sQt[(d+2)*64 + m] = t.z; sQt[(d+3)*64 + m] = t.w;
        }
    }

    float acc[4][8];
#pragma unroll
    for (int i = 0; i < 4; i++)
#pragma unroll
        for (int j = 0; j < 8; j++) acc[i][j] = 0.f;

    float rmax[4] = {-INFINITY, -INFINITY, -INFINITY, -INFINITY};
    float rsum[4] = {0.f, 0.f, 0.f, 0.f};

    for (int jt = 0; jt <= qt; jt++) {
        const int k0 = jt * 64;

        __syncthreads();

        {
            int m  = tid >> 2;
            int vb = tid & 3;
            const float* kp = g_k + (size_t)(k0 + m) * D_DIM + h * HD;
            const float* vp = g_v + (size_t)(k0 + m) * D_DIM + h * HD;
#pragma unroll
            for (int vv = vb; vv < 32; vv += 4) {
                float4 t = *(const float4*)(kp + vv * 4);
                int d = vv * 4;
                sKt[(d+0)*64 + m] = t.x; sKt[(d+1)*64 + m] = t.y;
                sKt[(d+2)*64 + m] = t.z; sKt[(d+3)*64 + m] = t.w;
                *(float4*)(sV + m * 132 + vv * 4) = *(const float4*)(vp + vv * 4);
            }
        }
        __syncthreads();

        float s[4][4];
#pragma unroll
        for (int i = 0; i < 4; i++)
#pragma unroll
            for (int j = 0; j < 4; j++) s[i][j] = 0.f;

#pragma unroll 8
        for (int d = 0; d < 128; d++) {
            float qa[4], kb[4];
#pragma unroll
            for (int i = 0; i < 4; i++) qa[i] = sQt[d*64 + ty*4 + i];
#pragma unroll
            for (int j = 0; j < 4; j++) kb[j] = sKt[d*64 + j*16 + tx];
#pragma unroll
            for (int i = 0; i < 4; i++)
#pragma unroll
                for (int j = 0; j < 4; j++)
                    s[i][j] += qa[i] * kb[j];
        }

        if (jt == qt) {
#pragma unroll
            for (int i = 0; i < 4; i++)
#pragma unroll
                for (int j = 0; j < 4; j++) {
                    int col = j * 16 + tx;
                    int row = ty * 4 + i;
                    s[i][j] = (col > row) ? -1.0e9f : s[i][j] * scale;
                }
        } else {
#pragma unroll
            for (int i = 0; i < 4; i++)
#pragma unroll
                for (int j = 0; j < 4; j++) s[i][j] *= scale;
        }

        float tm[4];
#pragma unroll
        for (int i = 0; i < 4; i++) {
            tm[i] = fmaxf(fmaxf(s[i][0], s[i][1]), fmaxf(s[i][2], s[i][3]));
#pragma unroll
            for (int off = 1; off < 16; off <<= 1)
                tm[i] = fmaxf(tm[i], __shfl_xor_sync(0xffffffffu, tm[i], off));
        }

        float nm[4], corr[4], p[4][4], rst[4];
#pragma unroll
        for (int i = 0; i < 4; i++) {
            nm[i]   = fmaxf(rmax[i], tm[i]);
            corr[i] = __expf(rmax[i] - nm[i]);
            float ps = 0.f;
#pragma unroll
            for (int j = 0; j < 4; j++) {
                p[i][j] = __expf(s[i][j] - nm[i]);
                ps += p[i][j];
            }
            rst[i] = ps;
#pragma unroll
            for (int off = 1; off < 16; off <<= 1)
                rst[i] += __shfl_xor_sync(0xffffffffu, rst[i], off);
            rsum[i] = rsum[i] * corr[i] + rst[i];
            rmax[i] = nm[i];
#pragma unroll
            for (int j = 0; j < 8; j++) acc[i][j] *= corr[i];
        }

#pragma unroll
        for (int j = 0; j < 4; j++)
#pragma unroll
            for (int i = 0; i < 4; i++)
                sPt[(j*16 + tx) * 65 + ty*4 + i] = p[i][j];

        __syncthreads();

#pragma unroll 4
        for (int c = 0; c < 64; c++) {
            float pv[4];
#pragma unroll
            for (int i = 0; i < 4; i++) pv[i] = sPt[c*65 + ty*4 + i];
            float4 v0 = *(const float4*)(sV + c*132 + tx*8);
            float4 v1 = *(const float4*)(sV + c*132 + tx*8 + 4);
#pragma unroll
            for (int i = 0; i < 4; i++) {
                acc[i][0] += pv[i] * v0.x; acc[i][1] += pv[i] * v0.y;
                acc[i][2] += pv[i] * v0.z; acc[i][3] += pv[i] * v0.w;
                acc[i][4] += pv[i] * v1.x; acc[i][5] += pv[i] * v1.y;
                acc[i][6] += pv[i] * v1.z; acc[i][7] += pv[i] * v1.w;
            }
        }
    }

#pragma unroll
    for (int i = 0; i < 4; i++) {
        float inv = 1.0f / rsum[i];
        float* op = g_att + (size_t)(q0 + ty*4 + i) * D_DIM + h * HD + tx * 8;
        *(float4*)(op)     = make_float4(acc[i][0]*inv, acc[i][1]*inv,
                                         acc[i][2]*inv, acc[i][3]*inv);
        *(float4*)(op + 4) = make_float4(acc[i][4]*inv, acc[i][5]*inv,
                                         acc[i][6]*inv, acc[i][7]*inv);
    }
}

// ---------------------------------------------------------------------------
// inputs: 0:x 1:cos 2:sin 3:mask 4:idx 5:cache_k 6:cache_v 7:wq 8:wk 9:wv 10:wo
// ---------------------------------------------------------------------------
extern "C" void kernel_launch(void* const* d_in, const int* in_sizes, int n_in,
                              void* d_out, int out_size)
{
    const float* x   = (const float*)d_in[0];
    const float* fc  = (const float*)d_in[1];
    const float* fs  = (const float*)d_in[2];
    const float* wq  = (const float*)d_in[7];
    const float* wk  = (const float*)d_in[8];
    const float* wv  = (const float*)d_in[9];
    const float* wo  = (const float*)d_in[10];
    float* out = (float*)d_out;

    cudaFuncSetAttribute(flash_kernel,
                         cudaFuncAttributeMaxDynamicSharedMemorySize,
                         FA_SMEM_BYTES);
    cudaFuncSetAttribute(qkv_gemm_kernel,
                         cudaFuncAttributeMaxDynamicSharedMemorySize,
                         GEMM_SMEM);
    cudaFuncSetAttribute(out_gemm_kernel,
                         cudaFuncAttributeMaxDynamicSharedMemorySize,
                         GEMM_SMEM);

    // device pointers of the scratch symbols (for prepass dst args)
    float *xp, *attp, *wqp, *wkp, *wvp, *wop, *attf;
    cudaGetSymbolAddress((void**)&xp,   g_xp);
    cudaGetSymbolAddress((void**)&attp, g_attp);
    cudaGetSymbolAddress((void**)&wqp,  g_wqp);
    cudaGetSymbolAddress((void**)&wkp,  g_wkp);
    cudaGetSymbolAddress((void**)&wvp,  g_wvp);
    cudaGetSymbolAddress((void**)&wop,  g_wop);
    cudaGetSymbolAddress((void**)&attf, g_att);

    const int nx8 = S_LEN * D_DIM / 8;      // 1,048,576
    const int nw8 = D_DIM * D_DIM / 8;      // 2,097,152
    tf32_permute_kernel<<<nx8 / 256, 256>>>(x,  xp,  nx8);
    tf32_permute_kernel<<<nw8 / 256, 256>>>(wq, wqp, nw8);
    tf32_permute_kernel<<<nw8 / 256, 256>>>(wk, wkp, nw8);
    tf32_permute_kernel<<<nw8 / 256, 256>>>(wv, wvp, nw8);
    tf32_permute_kernel<<<nw8 / 256, 256>>>(wo, wop, nw8);

    dim3 gQKV(D_DIM / TBN, S_LEN / TBM, 3);   // (32, 16, 3)
    qkv_gemm_kernel<<<gQKV, 256, GEMM_SMEM>>>();

    int nPairs = S_LEN * NH * (HD / 2);
    rope_kernel<<<(nPairs + 255) / 256, 256>>>(fc, fs);

    flash_kernel<<<dim3(S_LEN / 64, NH), 256, FA_SMEM_BYTES>>>();

    tf32_permute_kernel<<<nx8 / 256, 256>>>(attf, attp, nx8);

    dim3 gGemm(D_DIM / TBN, S_LEN / TBM);     // (32, 16)
    out_gemm_kernel<<<gGemm, 256, GEMM_SMEM>>>(out);
}